// round 16
// baseline (speedup 1.0000x reference)
#include <cuda_runtime.h>
#include <cuda_fp16.h>
#include <cstdint>
#include <cstddef>

// Problem constants
#define Bsz 4
#define Lsz 512
#define Dsz 768
#define Wsz 12
#define Ksz (Lsz * Wsz)
#define NTOK (Bsz * Ksz)     // 24576
#define BLROWS (Bsz * Lsz)   // 2048
#define FFD 3072
#define CATD 1536
#define QOFF 6291456u        // 2048*3072, Q2 offset

// fp16 weight buffer offsets (elements)
#define OFF_W1A 0u
#define OFF_W1B 2359296u
#define OFF_W2A 4718592u
#define OFF_W2B 7077888u
#define OFF_W3A 9437184u     // wo1 cols 0:768   -> [3072, 768]
#define OFF_W3B 11796480u    // wo1 cols 768:1536 -> [3072, 768]
#define OFF_W4  14155776u
#define WTOT    16515072u

// Static device scratch (allocation-free rule)
__device__ alignas(128) __half g_wh[WTOT];
__device__ alignas(128) __half g_h16[(size_t)BLROWS * Dsz];
__device__ alignas(128) __half g_hid[(size_t)BLROWS * 6144];  // L1 out only
__device__ alignas(128) __half g_se16[(size_t)BLROWS * CATD]; // relu'd se
__device__ alignas(128) float  g_q[(size_t)2 * BLROWS * FFD]; // Q1|Q2, fp32
__device__ float g_zero[FFD];
__device__ int g_is64;

// ---------------------------------------------------------------------------
// span_idx dtype detection (int64 vs int32)
// ---------------------------------------------------------------------------
__global__ void detect_idx_kernel(const unsigned int* __restrict__ sp, int nhalf) {
    __shared__ int s_any;
    if (threadIdx.x == 0) s_any = 0;
    __syncthreads();
    int found = 0;
    for (int i = threadIdx.x; i < nhalf; i += blockDim.x)
        if (sp[2 * i + 1] != 0u) found = 1;
    if (found) atomicOr(&s_any, 1);
    __syncthreads();
    if (threadIdx.x == 0) g_is64 = (s_any == 0) ? 1 : 0;
}

// ---------------------------------------------------------------------------
// Fused prep: h + all weights fp32 -> fp16, wo1 split into W3A|W3B
// ---------------------------------------------------------------------------
#define QC0 393216u
#define QC1 983040u
#define QC2 1572864u
#define QC3 2162688u
#define QC4 2752512u
#define QC5 3932160u
#define QC6 4521984u
#define PREP_BLOCKS ((QC6 + 255u) / 256u)

__global__ void prep_kernel(const float* __restrict__ h,
                            const float* __restrict__ ws1, const float* __restrict__ we1,
                            const float* __restrict__ ws2, const float* __restrict__ we2,
                            const float* __restrict__ wo1, const float* __restrict__ wo2,
                            __half* __restrict__ h16, __half* __restrict__ wh)
{
    unsigned int t = blockIdx.x * 256u + threadIdx.x;
    if (t >= QC6) return;
    const float* src;
    __half* dst;
    unsigned int soff, doff;
    if (t < QC0)      { src = h;   dst = h16;          soff = t;       doff = soff; }
    else if (t < QC1) { src = ws1; dst = wh + OFF_W1A; soff = t - QC0; doff = soff; }
    else if (t < QC2) { src = we1; dst = wh + OFF_W1B; soff = t - QC1; doff = soff; }
    else if (t < QC3) { src = ws2; dst = wh + OFF_W2A; soff = t - QC2; doff = soff; }
    else if (t < QC4) { src = we2; dst = wh + OFF_W2B; soff = t - QC3; doff = soff; }
    else if (t < QC5) {
        src = wo1; soff = t - QC4;
        unsigned qrow = soff / 384u, qcol = soff - qrow * 384u;
        if (qcol < 192u) { dst = wh + OFF_W3A; doff = qrow * 192u + qcol; }
        else             { dst = wh + OFF_W3B; doff = qrow * 192u + qcol - 192u; }
    }
    else              { src = wo2; dst = wh + OFF_W4;  soff = t - QC5; doff = soff; }
    float4 v = ((const float4*)src)[soff];
    __half hh[4] = {__float2half_rn(v.x), __float2half_rn(v.y),
                    __float2half_rn(v.z), __float2half_rn(v.w)};
    ((uint2*)dst)[doff] = *(uint2*)hh;
}

// ---------------------------------------------------------------------------
// PTX helpers
// ---------------------------------------------------------------------------
__device__ __forceinline__ uint32_t smem_u32(const void* p) {
    return (uint32_t)__cvta_generic_to_shared(p);
}
__device__ __forceinline__ void ldm_x4(uint32_t* r, uint32_t addr) {
    asm volatile("ldmatrix.sync.aligned.m8n8.x4.shared.b16 {%0,%1,%2,%3}, [%4];"
                 : "=r"(r[0]), "=r"(r[1]), "=r"(r[2]), "=r"(r[3]) : "r"(addr));
}
__device__ __forceinline__ void mma_f16(float* d, const uint32_t* a, const uint32_t* b) {
    asm volatile(
        "mma.sync.aligned.m16n8k16.row.col.f32.f16.f16.f32 "
        "{%0,%1,%2,%3},{%4,%5,%6,%7},{%8,%9},{%0,%1,%2,%3};"
        : "+f"(d[0]), "+f"(d[1]), "+f"(d[2]), "+f"(d[3])
        : "r"(a[0]), "r"(a[1]), "r"(a[2]), "r"(a[3]), "r"(b[0]), "r"(b[1]));
}
__device__ __forceinline__ void cp16(uint32_t dst, const void* src) {
    asm volatile("cp.async.cg.shared.global [%0], [%1], 16;" :: "r"(dst), "l"(src));
}

// ---------------------------------------------------------------------------
// fp16 tensor GEMM (NT): unchanged R15 workhorse for L1/L2/Q.
// ---------------------------------------------------------------------------
#define SKB 144

template<int BN, int NTHR>
__global__ __launch_bounds__(NTHR, (BN == 128) ? 2 : 1)
void gemm16_kernel(const __half* __restrict__ A,
                   const __half* __restrict__ B,
                   const float* __restrict__ bias1,
                   const float* __restrict__ bias2, int nsplit,
                   float* __restrict__ Cf,
                   __half* __restrict__ Ch,
                   int N, int K, int lda, int ldc, int mode,
                   int zAoff, int zBoff, int zCoff, int zBias)
{
    constexpr int NWARP = NTHR / 32;
    constexpr int WM    = 128 / (NWARP / 4);
    constexpr int WN    = BN / 4;
    constexpr int MI    = WM / 16;
    constexpr int NP    = WN / 16;
    constexpr int NF    = WN / 8;
    constexpr int TILEA = 128 * SKB;
    constexpr int TILEB = BN * SKB;
    constexpr int STAGE = TILEA + TILEB;

    extern __shared__ char smem[];
    const uint32_t sbase = smem_u32(smem);

    const int tid  = threadIdx.x;
    const int lane = tid & 31;
    const int wid  = tid >> 5;
    const int wm   = (wid >> 2) * WM;
    const int wn   = (wid & 3) * WN;
    const int bm   = blockIdx.y << 7;
    const int bn   = blockIdx.x * BN;
    const int z    = blockIdx.z;

    const __half* aSrc = A + (size_t)z * zAoff + (size_t)bm * lda;
    const __half* bSrc = B + (size_t)z * zBoff + (size_t)bn * K;

    float acc[MI][NF][4];
#pragma unroll
    for (int i = 0; i < MI; i++)
#pragma unroll
        for (int j = 0; j < NF; j++)
#pragma unroll
            for (int r = 0; r < 4; r++) acc[i][j][r] = 0.f;

    const int nk = K >> 6;

    auto issue = [&](int kt) {
        const uint32_t st = sbase + (kt % 3) * STAGE;
        const int kb = kt << 6;
#pragma unroll
        for (int c = tid; c < 1024; c += NTHR) {
            const int row = c >> 3, ch = c & 7;
            cp16(st + (uint32_t)row * SKB + ch * 16,
                 aSrc + (size_t)row * lda + kb + ch * 8);
        }
#pragma unroll
        for (int c = tid; c < BN * 8; c += NTHR) {
            const int row = c >> 3, ch = c & 7;
            cp16(st + TILEA + (uint32_t)row * SKB + ch * 16,
                 bSrc + (size_t)row * K + kb + ch * 8);
        }
    };

    const int aq    = lane >> 3;
    const int arow  = ((aq & 1) << 3) + (lane & 7);
    const int acol  = (aq >> 1) << 3;
    const int brow4 = ((lane >> 4) << 3) + (lane & 7);
    const int bcol4 = ((lane >> 3) & 1) << 3;

    uint32_t a[2][MI][4], bb[2][NP][4];

    auto ldfrag = [&](uint32_t st, int kk, int fb) {
#pragma unroll
        for (int mi = 0; mi < MI; mi++) {
            const uint32_t off = (uint32_t)(wm + mi * 16 + arow) * SKB + (kk + acol) * 2;
            ldm_x4(a[fb][mi], st + off);
        }
#pragma unroll
        for (int p = 0; p < NP; p++) {
            const uint32_t off = (uint32_t)(wn + p * 16 + brow4) * SKB + (kk + bcol4) * 2;
            ldm_x4(bb[fb][p], st + TILEA + off);
        }
    };

    issue(0);
    asm volatile("cp.async.commit_group;" ::: "memory");
    issue(1);
    asm volatile("cp.async.commit_group;" ::: "memory");

    for (int kt = 0; kt < nk; kt++) {
        asm volatile("cp.async.wait_group 1;" ::: "memory");
        __syncthreads();
        if (kt + 2 < nk) issue(kt + 2);
        asm volatile("cp.async.commit_group;" ::: "memory");

        const uint32_t st = sbase + (kt % 3) * STAGE;

        ldfrag(st, 0, 0);
#pragma unroll
        for (int j = 0; j < 4; j++) {
            const int cur = j & 1;
            if (j < 3) ldfrag(st, (j + 1) * 16, cur ^ 1);
#pragma unroll
            for (int mi = 0; mi < MI; mi++)
#pragma unroll
                for (int p = 0; p < NP; p++) {
                    mma_f16(acc[mi][2 * p],     a[cur][mi], &bb[cur][p][0]);
                    mma_f16(acc[mi][2 * p + 1], a[cur][mi], &bb[cur][p][2]);
                }
        }
    }

    float* Cfz = Cf ? Cf + (size_t)z * zCoff : nullptr;
    __half* Chz = Ch ? Ch + (size_t)z * zCoff : nullptr;
    const float* bA = (zBias && z) ? bias2 : bias1;

    const int lr = lane >> 2;
    const int lc = (lane & 3) * 2;
#pragma unroll
    for (int mi = 0; mi < MI; mi++) {
#pragma unroll
        for (int ni = 0; ni < NF; ni++) {
            const int gm = bm + wm + mi * 16 + lr;
            const int gc = bn + wn + ni * 8 + lc;
            const float b0 = (gc < nsplit)     ? bA[gc]     : bias2[gc - nsplit];
            const float b1 = (gc + 1 < nsplit) ? bA[gc + 1] : bias2[gc + 1 - nsplit];
            float v0 = acc[mi][ni][0] + b0;
            float v1 = acc[mi][ni][1] + b1;
            float v2 = acc[mi][ni][2] + b0;
            float v3 = acc[mi][ni][3] + b1;
            if (mode == 0) {
                *(float2*)(Cfz + (size_t)gm * ldc + gc)       = make_float2(v0, v1);
                *(float2*)(Cfz + (size_t)(gm + 8) * ldc + gc) = make_float2(v2, v3);
            } else {
                if (mode == 1) {
                    v0 = fmaxf(v0, 0.f); v1 = fmaxf(v1, 0.f);
                    v2 = fmaxf(v2, 0.f); v3 = fmaxf(v3, 0.f);
                }
                __half p01[2] = {__float2half_rn(v0), __float2half_rn(v1)};
                __half p23[2] = {__float2half_rn(v2), __float2half_rn(v3)};
                *(uint32_t*)(Chz + (size_t)gm * ldc + gc)       = *(uint32_t*)p01;
                *(uint32_t*)(Chz + (size_t)(gm + 8) * ldc + gc) = *(uint32_t*)p23;
            }
        }
    }
}

// ---------------------------------------------------------------------------
// Fused L4: out[24576,768] = relu(Q1[s_r]+Q2[e_r]+bo1) @ wo2^T + bo2.
// Block 128x256x32, 8 warps (2x4), warp 64x64. Q1/Q2 fp32 row-gathered via
// cp.async (3-stage); in-smem convert (add+bias+relu->fp16) into a
// double-buffered A tile; standard ldmatrix/MMA path. Arithmetic identical
// to the old combine kernel -> rel_err unchanged.
// ---------------------------------------------------------------------------
#define F32ROW 144                    // 32 floats (128B) + 16B pad
#define FQT   (128 * F32ROW)          // 18432 per Q tile
#define FBT   (256 * 80)              // 20480 B tile (fp16, 80B rows)
#define FSTAGE (2 * FQT + FBT)        // 57344
#define FA16  (128 * 80)              // 10240 fp16 A tile
#define FSMEM (3 * FSTAGE + 2 * FA16) // 192512

__global__ __launch_bounds__(256, 1)
void l4_fused_kernel(const float* __restrict__ q,
                     const __half* __restrict__ W,   // wo2 fp16 [768, 3072]
                     const void* __restrict__ span,
                     const float* __restrict__ bo1,
                     const float* __restrict__ bo2,
                     float* __restrict__ out)
{
    extern __shared__ char smem[];
    const uint32_t sbase = smem_u32(smem);
    const uint32_t abase = sbase + 3 * FSTAGE;

    const int tid  = threadIdx.x;
    const int lane = tid & 31;
    const int wid  = tid >> 5;
    const int wm   = (wid >> 2) * 64;
    const int wn   = (wid & 3) * 64;
    const int bm   = blockIdx.y << 7;
    const int bn   = blockIdx.x << 8;   // BN=256

    // Per-thread gathered Q row pointers (rows r0, r0+32, r0+64, r0+96)
    const float* q1p[4];
    const float* q2p[4];
    {
        const int r0 = tid >> 3;
#pragma unroll
        for (int i = 0; i < 4; i++) {
            const int gm = bm + r0 + 32 * i;
            const int b = gm / Ksz;
            long long s, e;
            if (g_is64) {
                const long long* sp = (const long long*)span;
                s = sp[2 * (size_t)gm]; e = sp[2 * (size_t)gm + 1];
            } else {
                const int* sp = (const int*)span;
                s = sp[2 * (size_t)gm]; e = sp[2 * (size_t)gm + 1];
            }
            q1p[i] = q + ((size_t)(b * Lsz) + s) * FFD;
            q2p[i] = q + QOFF + ((size_t)(b * Lsz) + e) * FFD;
        }
    }
    const __half* bSrc = W + (size_t)bn * FFD;

    float acc[4][8][4];
#pragma unroll
    for (int i = 0; i < 4; i++)
#pragma unroll
        for (int j = 0; j < 8; j++)
#pragma unroll
            for (int r = 0; r < 4; r++) acc[i][j][r] = 0.f;

    const int nk = FFD / 32;   // 96

    auto issue = [&](int kt) {
        const uint32_t st = sbase + (kt % 3) * FSTAGE;
        const int kb = kt << 5;
        const int qch = tid & 7;                       // 16B chunk in 128B row
        const uint32_t qd = (uint32_t)(tid >> 3) * F32ROW + qch * 16;
#pragma unroll
        for (int i = 0; i < 4; i++) {
            cp16(st + qd + i * (32 * F32ROW),       q1p[i] + kb + qch * 4);
            cp16(st + FQT + qd + i * (32 * F32ROW), q2p[i] + kb + qch * 4);
        }
        const int bch  = tid & 3;                      // 16B chunk in 64B row
        const int brw0 = tid >> 2;                     // 0..63
#pragma unroll
        for (int i = 0; i < 4; i++) {
            const int row = brw0 + 64 * i;
            cp16(st + 2 * FQT + (uint32_t)row * 80 + bch * 16,
                 bSrc + (size_t)row * FFD + kb + bch * 8);
        }
    };

    // ldmatrix lane mapping
    const int aq    = lane >> 3;
    const int arow  = ((aq & 1) << 3) + (lane & 7);
    const int acol  = (aq >> 1) << 3;
    const int brow4 = ((lane >> 4) << 3) + (lane & 7);
    const int bcol4 = ((lane >> 3) & 1) << 3;

    uint32_t a[2][4][4], bb[2][4][4];

    auto ldfrag = [&](uint32_t a16, uint32_t bst, int kk, int fb) {
#pragma unroll
        for (int mi = 0; mi < 4; mi++) {
            const uint32_t off = (uint32_t)(wm + mi * 16 + arow) * 80 + (kk + acol) * 2;
            ldm_x4(a[fb][mi], a16 + off);
        }
#pragma unroll
        for (int p = 0; p < 4; p++) {
            const uint32_t off = (uint32_t)(wn + p * 16 + brow4) * 80 + (kk + bcol4) * 2;
            ldm_x4(bb[fb][p], bst + off);
        }
    };

    issue(0);
    asm volatile("cp.async.commit_group;" ::: "memory");
    issue(1);
    asm volatile("cp.async.commit_group;" ::: "memory");

    for (int kt = 0; kt < nk; kt++) {
        asm volatile("cp.async.wait_group 1;" ::: "memory");
        __syncthreads();

        // Convert: A16[kt&1][row][c] = fp16(relu(Q1 + Q2 + bo1)), 16 cols/thread
        {
            const char* stc = smem + (kt % 3) * FSTAGE;
            char* a16c = smem + 3 * FSTAGE + (kt & 1) * FA16;
            const int row  = tid >> 1;
            const int half = tid & 1;
            const int kb   = kt << 5;
            const float* q1s = (const float*)(stc + (size_t)row * F32ROW + half * 64);
            const float* q2s = (const float*)(stc + FQT + (size_t)row * F32ROW + half * 64);
            const float* bi  = bo1 + kb + half * 16;
            __half hv[16];
#pragma unroll
            for (int j = 0; j < 4; j++) {
                float4 x = ((const float4*)q1s)[j];
                float4 y = ((const float4*)q2s)[j];
                float4 bv = *(const float4*)(bi + j * 4);
                hv[j*4+0] = __float2half_rn(fmaxf(x.x + y.x + bv.x, 0.f));
                hv[j*4+1] = __float2half_rn(fmaxf(x.y + y.y + bv.y, 0.f));
                hv[j*4+2] = __float2half_rn(fmaxf(x.z + y.z + bv.z, 0.f));
                hv[j*4+3] = __float2half_rn(fmaxf(x.w + y.w + bv.w, 0.f));
            }
            uint4* dst = (uint4*)(a16c + (size_t)row * 80 + half * 32);
            dst[0] = ((uint4*)hv)[0];
            dst[1] = ((uint4*)hv)[1];
        }

        if (kt + 2 < nk) issue(kt + 2);
        asm volatile("cp.async.commit_group;" ::: "memory");
        __syncthreads();

        const uint32_t a16 = abase + (kt & 1) * FA16;
        const uint32_t bst = sbase + (kt % 3) * FSTAGE + 2 * FQT;

        ldfrag(a16, bst, 0, 0);
#pragma unroll
        for (int j = 0; j < 2; j++) {
            const int cur = j & 1;
            if (j < 1) ldfrag(a16, bst, 16, 1);
#pragma unroll
            for (int mi = 0; mi < 4; mi++)
#pragma unroll
                for (int p = 0; p < 4; p++) {
                    mma_f16(acc[mi][2 * p],     a[cur][mi], &bb[cur][p][0]);
                    mma_f16(acc[mi][2 * p + 1], a[cur][mi], &bb[cur][p][2]);
                }
        }
    }

    // Epilogue: fp32 out + bo2
    const int lr = lane >> 2;
    const int lc = (lane & 3) * 2;
#pragma unroll
    for (int mi = 0; mi < 4; mi++) {
#pragma unroll
        for (int ni = 0; ni < 8; ni++) {
            const int gm = bm + wm + mi * 16 + lr;
            const int gc = bn + wn + ni * 8 + lc;
            const float b0 = bo2[gc], b1 = bo2[gc + 1];
            *(float2*)(out + (size_t)gm * Dsz + gc) =
                make_float2(acc[mi][ni][0] + b0, acc[mi][ni][1] + b1);
            *(float2*)(out + (size_t)(gm + 8) * Dsz + gc) =
                make_float2(acc[mi][ni][2] + b0, acc[mi][ni][3] + b1);
        }
    }
}

// ---------------------------------------------------------------------------
// Launch: detect(1), prep(2), L1(3), L2(4), Q(5), L4fused(6 = profiled)
// ---------------------------------------------------------------------------
extern "C" void kernel_launch(void* const* d_in, const int* in_sizes, int n_in,
                              void* d_out, int out_size)
{
    const float* h   = (const float*)d_in[0];
    const void*  sp  = d_in[1];
    const float* ws1 = (const float*)d_in[2];
    const float* bs1 = (const float*)d_in[3];
    const float* ws2 = (const float*)d_in[4];
    const float* bs2 = (const float*)d_in[5];
    const float* we1 = (const float*)d_in[6];
    const float* be1 = (const float*)d_in[7];
    const float* we2 = (const float*)d_in[8];
    const float* be2 = (const float*)d_in[9];
    const float* wo1 = (const float*)d_in[10];
    const float* bo1 = (const float*)d_in[11];
    const float* wo2 = (const float*)d_in[12];
    const float* bo2 = (const float*)d_in[13];
    float* out = (float*)d_out;

    __half *wh, *h16, *hid, *se;
    float *qbuf, *zeros;
    cudaGetSymbolAddress((void**)&wh,    g_wh);
    cudaGetSymbolAddress((void**)&h16,   g_h16);
    cudaGetSymbolAddress((void**)&hid,   g_hid);
    cudaGetSymbolAddress((void**)&se,    g_se16);
    cudaGetSymbolAddress((void**)&qbuf,  g_q);
    cudaGetSymbolAddress((void**)&zeros, g_zero);

    const int SM256 = 3 * (128 * SKB + 256 * SKB);   // 165888
    const int SM128 = 3 * (128 * SKB + 128 * SKB);   // 110592
    cudaFuncSetAttribute((const void*)gemm16_kernel<256, 256>,
                         cudaFuncAttributeMaxDynamicSharedMemorySize, SM256);
    cudaFuncSetAttribute((const void*)gemm16_kernel<128, 256>,
                         cudaFuncAttributeMaxDynamicSharedMemorySize, SM128);
    cudaFuncSetAttribute((const void*)l4_fused_kernel,
                         cudaFuncAttributeMaxDynamicSharedMemorySize, FSMEM);

    // #1: span dtype detect
    detect_idx_kernel<<<1, 256>>>((const unsigned int*)sp, NTOK);

    // #2: fp32->fp16 conversions
    prep_kernel<<<PREP_BLOCKS, 256>>>(h, ws1, we1, ws2, we2, wo1, wo2, h16, wh);

    // #3: L1 fused start|end layer1: hid[2048,6144] = h @ [ws1;we1]^T, relu
    gemm16_kernel<256, 256><<<dim3(6144/256, BLROWS/128, 1), 256, SM256>>>(
        h16, wh + OFF_W1A, bs1, be1, FFD, nullptr, hid,
        6144, Dsz, Dsz, 6144, 1, 0, 0, 0, 0);

    // #4: L2 batched (z=0 start, z=1 end) -> se_relu fp16 [2048, 1536]
    gemm16_kernel<128, 256><<<dim3(Dsz/128, BLROWS/128, 2), 256, SM128>>>(
        hid, wh + OFF_W2A, bs2, be2, Dsz, nullptr, se,
        Dsz, FFD, 6144, CATD, 1, FFD, (int)(OFF_W2B - OFF_W2A), Dsz, 1);

    // #5: Q batched (z=0: se[:, :768]@W3A^T; z=1: se[:, 768:]@W3B^T), fp32, no bias
    gemm16_kernel<256, 256><<<dim3(FFD/256, BLROWS/128, 2), 256, SM256>>>(
        se, wh + OFF_W3A, zeros, zeros, FFD, qbuf, nullptr,
        FFD, Dsz, CATD, FFD, 0, Dsz, (int)(OFF_W3B - OFF_W3A), (int)QOFF, 1);

    // #6: fused L4 (dominant, profiled): gather+combine+GEMM
    l4_fused_kernel<<<dim3(Dsz/256, NTOK/128, 1), 256, FSMEM>>>(
        qbuf, wh + OFF_W4, sp, bo1, bo2, out);
}